// round 10
// baseline (speedup 1.0000x reference)
#include <cuda_runtime.h>
#include <math.h>
#include <stdint.h>

#define B_ 8
#define L_ 4096
#define D_ 768
#define Y_ 2048
#define NLB 64                  // l-blocks (L/64)
#define NTILES 8192             // 64 lblk * 16 yblk * 8 b

// ---------------- device scratch (no allocations allowed) ----------------
__device__ int8_t g_X1[(size_t)B_ * L_ * D_];
__device__ int8_t g_X0[(size_t)B_ * L_ * D_];
__device__ int8_t g_U1[(size_t)Y_ * D_];
__device__ int8_t g_U0[(size_t)Y_ * D_];
__device__ int8_t g_F1[(size_t)Y_ * D_];
__device__ int8_t g_F0[(size_t)Y_ * D_];
__device__ float g_sx[(size_t)B_ * L_];
__device__ float g_su[Y_];
__device__ float g_sf[Y_];
__device__ float g_pm[(size_t)B_ * Y_ * NLB];
__device__ float g_ps[(size_t)B_ * Y_ * NLB];
__device__ float g_pn[(size_t)B_ * Y_ * NLB];
__device__ float g_y[(size_t)B_ * Y_];
__device__ float g_loss;

// ---------------- helpers ----------------
__device__ __forceinline__ uint32_t smem_u32(const void* p) {
    uint32_t a;
    asm("{ .reg .u64 t; cvta.to.shared.u64 t, %1; cvt.u32.u64 %0, t; }" : "=r"(a) : "l"(p));
    return a;
}
#define SWZ128(x) ((x) ^ (((x) >> 3) & 0x70))

#define CP16(dst, src) \
    asm volatile("cp.async.cg.shared.global [%0], [%1], 16;" :: "r"(dst), "l"(src))
#define CPCOMMIT() asm volatile("cp.async.commit_group;" ::: "memory")
#define CPWAIT1() asm volatile("cp.async.wait_group 1;" ::: "memory")
#define CPWAIT0() asm volatile("cp.async.wait_group 0;" ::: "memory")

__device__ __forceinline__ void ldsm_x4(uint32_t* r, uint32_t addr) {
    asm volatile("ldmatrix.sync.aligned.m8n8.x4.shared.b16 {%0,%1,%2,%3}, [%4];"
        : "=r"(r[0]), "=r"(r[1]), "=r"(r[2]), "=r"(r[3]) : "r"(addr));
}
// s8 IMMA m16n8k32, s32 accumulate (byte-layout identical to bf16 m16n8k16)
#define MMA_S8(d, a, b0, b1)                                                  \
    asm volatile("mma.sync.aligned.m16n8k32.row.col.s32.s8.s8.s32 "           \
        "{%0,%1,%2,%3}, {%4,%5,%6,%7}, {%8,%9}, {%0,%1,%2,%3};"               \
        : "+r"((d)[0]), "+r"((d)[1]), "+r"((d)[2]), "+r"((d)[3])              \
        : "r"((a)[0]), "r"((a)[1]), "r"((a)[2]), "r"((a)[3]),                 \
          "r"(b0), "r"(b1))

// ---------------- per-row 15-bit quantization into two s8 limbs ----------
// row value v = scale * (128*hi + lo), |lo| <= 64
__global__ void __launch_bounds__(256)
quant_kernel(const float* __restrict__ in, int8_t* __restrict__ q1,
             int8_t* __restrict__ q0, float* __restrict__ scale, int rows) {
    const int wid = threadIdx.x >> 5, lane = threadIdx.x & 31;
    const int row = blockIdx.x * 8 + wid;
    if (row >= rows) return;
    const float4* src = (const float4*)(in) + (size_t)row * 192;
    float4 v[6];
    float m = 0.f;
#pragma unroll
    for (int j = 0; j < 6; j++) {
        v[j] = src[j * 32 + lane];
        m = fmaxf(m, fmaxf(fmaxf(fabsf(v[j].x), fabsf(v[j].y)),
                           fmaxf(fabsf(v[j].z), fabsf(v[j].w))));
    }
#pragma unroll
    for (int s = 16; s > 0; s >>= 1) m = fmaxf(m, __shfl_xor_sync(0xffffffffu, m, s));
    m = fmaxf(m, 1e-30f);
    const float inv = 16256.f / m;
    if (lane == 0) scale[row] = m / 16256.f;
    int* o1 = (int*)q1 + (size_t)row * 192;
    int* o0 = (int*)q0 + (size_t)row * 192;
#pragma unroll
    for (int j = 0; j < 6; j++) {
        int p1 = 0, p0 = 0;
        const float vals[4] = { v[j].x, v[j].y, v[j].z, v[j].w };
#pragma unroll
        for (int e = 0; e < 4; e++) {
            const int X = __float2int_rn(vals[e] * inv);
            const int hi = (X + 64) >> 7;
            const int lo = X - (hi << 7);
            p1 |= (hi & 255) << (e * 8);
            p0 |= (lo & 255) << (e * 8);
        }
        o1[j * 32 + lane] = p1;
        o0[j * 32 + lane] = p0;
    }
}

// ------- persistent dual int8 GEMM + register partial softmax -------------
// CTA tile 128y x 64l, 512 threads (16 warps: 4y x 4l grid of 32y x 16l).
// Stage = k-chunk 128 bytes: U1,U0,F1,F0 (16KB ea) + X1,X0 (8KB ea) = 80KB x2.
#define A16K 16384
#define X8K 8192
#define XOFF (4 * A16K)            // 65536
#define STAGE_B 81920
#define PART_OFF (2 * STAGE_B)     // 163840
#define SMEM_TOT (PART_OFF + 3 * 128 * 4 * 4)   // 169984

__device__ __forceinline__ void issue_stage(uint32_t sb, int ls,
                                            int tid, int stride) {
    const int tl = ls / 6, ks = ls - tl * 6;
    const int t = blockIdx.x + tl * stride;
    const int lblk = t & 63, yblk = (t >> 6) & 15, b = t >> 10;
    const int8_t* asrc[4] = {
        g_U1 + (size_t)(yblk * 128) * D_, g_U0 + (size_t)(yblk * 128) * D_,
        g_F1 + (size_t)(yblk * 128) * D_, g_F0 + (size_t)(yblk * 128) * D_
    };
    const int8_t* xsrc[2] = {
        g_X1 + ((size_t)b * L_ + lblk * 64) * D_,
        g_X0 + ((size_t)b * L_ + lblk * 64) * D_
    };
    const uint32_t bufb = (uint32_t)(ls & 1) * STAGE_B;
#pragma unroll
    for (int j = 0; j < 8; j++) {           // A tiles: 4096 chunks
        const int gi = j * 512 + tid;
        const int tt = gi >> 10;
        const int ci = gi & 1023;
        const int row = ci >> 3, c16 = ci & 7;
        const char* src = (const char*)(asrc[tt] + (size_t)row * D_ + ks * 128) + c16 * 16;
        const uint32_t dst = sb + bufb + tt * A16K + SWZ128(row * 128 + c16 * 16);
        CP16(dst, src);
    }
#pragma unroll
    for (int j = 0; j < 2; j++) {           // X tiles: 1024 chunks
        const int gi = j * 512 + tid;
        const int tt = gi >> 9;
        const int ci = gi & 511;
        const int row = ci >> 3, c16 = ci & 7;
        const char* src = (const char*)(xsrc[tt] + (size_t)row * D_ + ks * 128) + c16 * 16;
        const uint32_t dst = sb + bufb + XOFF + tt * X8K + SWZ128(row * 128 + c16 * 16);
        CP16(dst, src);
    }
    CPCOMMIT();
}

__global__ void __launch_bounds__(512, 1)
gemm_kernel() {
    extern __shared__ char smem[];
    const uint32_t sb = smem_u32(smem);
    float* partm = (float*)(smem + PART_OFF);          // [128][4]
    float* parts = partm + 128 * 4;
    float* partn = parts + 128 * 4;

    const int tid = threadIdx.x, lane = tid & 31, wid = tid >> 5;
    const int stride = gridDim.x;
    const int myN = (NTILES - blockIdx.x + stride - 1) / stride;
    const int total = 6 * myN;

    const int my = (wid & 3) * 32;
    const int nl = (wid >> 2) * 16;
    const int wcol = wid >> 2;

    const uint32_t aByte = (uint32_t)((my + (lane & 15)) * 128 + ((lane >> 4) << 4));
    const uint32_t bByte = (uint32_t)((nl + (lane & 7) + ((lane >> 4) & 1) * 8) * 128
                                      + (((lane >> 3) & 1) << 4));

    int att1[2][2][4], att2[2][2][4], tt1[2][2][4], tt2[2][2][4];
#pragma unroll
    for (int mt = 0; mt < 2; mt++)
#pragma unroll
        for (int nt = 0; nt < 2; nt++)
#pragma unroll
            for (int r = 0; r < 4; r++) {
                att1[mt][nt][r] = 0; att2[mt][nt][r] = 0;
                tt1[mt][nt][r] = 0;  tt2[mt][nt][r] = 0;
            }

    issue_stage(sb, 0, tid, stride);
    if (total > 1) issue_stage(sb, 1, tid, stride);

    for (int ls = 0; ls < total; ls++) {
        if (ls == total - 1) { CPWAIT0(); } else { CPWAIT1(); }
        __syncthreads();
        const uint32_t bufo = sb + (uint32_t)(ls & 1) * STAGE_B;

#pragma unroll
        for (int kk = 0; kk < 4; kk++) {
            uint32_t b1[4], b0[4];
            {
                const uint32_t sw = SWZ128(bByte + (uint32_t)(kk * 32));
                ldsm_x4(b1, bufo + XOFF + sw);
                ldsm_x4(b0, bufo + XOFF + X8K + sw);
            }
#pragma unroll
            for (int mt = 0; mt < 2; mt++) {
                const uint32_t sw = SWZ128(aByte + (uint32_t)(mt * 16 * 128 + kk * 32));
                uint32_t u1[4], u0[4], f1[4], f0[4];
                ldsm_x4(u1, bufo + 0 * A16K + sw);
                ldsm_x4(u0, bufo + 1 * A16K + sw);
                ldsm_x4(f1, bufo + 2 * A16K + sw);
                ldsm_x4(f0, bufo + 3 * A16K + sw);
                // att: hh -> acc1, hl + lh -> acc2
                MMA_S8(att1[mt][0], u1, b1[0], b1[1]);
                MMA_S8(att1[mt][1], u1, b1[2], b1[3]);
                MMA_S8(att2[mt][0], u1, b0[0], b0[1]);
                MMA_S8(att2[mt][1], u1, b0[2], b0[3]);
                MMA_S8(att2[mt][0], u0, b1[0], b1[1]);
                MMA_S8(att2[mt][1], u0, b1[2], b1[3]);
                // t
                MMA_S8(tt1[mt][0], f1, b1[0], b1[1]);
                MMA_S8(tt1[mt][1], f1, b1[2], b1[3]);
                MMA_S8(tt2[mt][0], f1, b0[0], b0[1]);
                MMA_S8(tt2[mt][1], f1, b0[2], b0[3]);
                MMA_S8(tt2[mt][0], f0, b1[0], b1[1]);
                MMA_S8(tt2[mt][1], f0, b1[2], b1[3]);
            }
        }
        __syncthreads();
        if (ls + 2 < total) issue_stage(sb, ls + 2, tid, stride);

        if ((ls % 6) == 5) {
            // ---- epilogue: dequant + register partial softmax ----
            const int t = blockIdx.x + (ls / 6) * stride;
            const int lblk = t & 63, yblk = (t >> 6) & 15, b = t >> 10;
            const int ybase = yblk * 128;
            const int l0 = lblk * 64;
            // sx for this thread's 4 columns (same across mt/half)
            float sxv[4];
#pragma unroll
            for (int nt = 0; nt < 2; nt++)
#pragma unroll
                for (int j = 0; j < 2; j++)
                    sxv[nt * 2 + j] =
                        g_sx[(size_t)b * L_ + l0 + nl + nt * 8 + (lane & 3) * 2 + j];
#pragma unroll
            for (int mt = 0; mt < 2; mt++) {
#pragma unroll
                for (int half = 0; half < 2; half++) {
                    const int row = my + mt * 16 + half * 8 + (lane >> 2);
                    const float su = g_su[ybase + row];
                    const float sf = g_sf[ybase + row];
                    float a[4], tv[4];
#pragma unroll
                    for (int nt = 0; nt < 2; nt++)
#pragma unroll
                        for (int j = 0; j < 2; j++) {
                            const int ri = half * 2 + j;
                            const float da = 16384.f * (float)att1[mt][nt][ri]
                                           + 128.f * (float)att2[mt][nt][ri];
                            const float dt = 16384.f * (float)tt1[mt][nt][ri]
                                           + 128.f * (float)tt2[mt][nt][ri];
                            a[nt * 2 + j] = su * sxv[nt * 2 + j] * da;
                            tv[nt * 2 + j] = sf * sxv[nt * 2 + j] * dt;
                        }
                    float m = fmaxf(fmaxf(a[0], a[1]), fmaxf(a[2], a[3]));
                    m = fmaxf(m, __shfl_xor_sync(0xffffffffu, m, 1));
                    m = fmaxf(m, __shfl_xor_sync(0xffffffffu, m, 2));
                    float S = 0.f, N = 0.f;
#pragma unroll
                    for (int j = 0; j < 4; j++) {
                        const float e = __expf(a[j] - m);
                        S += e;
                        N += e * tv[j];
                    }
                    S += __shfl_xor_sync(0xffffffffu, S, 1);
                    S += __shfl_xor_sync(0xffffffffu, S, 2);
                    N += __shfl_xor_sync(0xffffffffu, N, 1);
                    N += __shfl_xor_sync(0xffffffffu, N, 2);
                    if ((lane & 3) == 0) {
                        partm[row * 4 + wcol] = m;
                        parts[row * 4 + wcol] = S;
                        partn[row * 4 + wcol] = N;
                    }
                }
            }
            __syncthreads();
            if (tid < 128) {
                const float m0 = partm[tid * 4 + 0], m1 = partm[tid * 4 + 1];
                const float m2 = partm[tid * 4 + 2], m3 = partm[tid * 4 + 3];
                const float gm = fmaxf(fmaxf(m0, m1), fmaxf(m2, m3));
                const float e0 = __expf(m0 - gm), e1 = __expf(m1 - gm);
                const float e2 = __expf(m2 - gm), e3 = __expf(m3 - gm);
                const float S = parts[tid * 4 + 0] * e0 + parts[tid * 4 + 1] * e1
                              + parts[tid * 4 + 2] * e2 + parts[tid * 4 + 3] * e3;
                const float N = partn[tid * 4 + 0] * e0 + partn[tid * 4 + 1] * e1
                              + partn[tid * 4 + 2] * e2 + partn[tid * 4 + 3] * e3;
                const size_t idx = ((size_t)b * Y_ + ybase + tid) * NLB + lblk;
                g_pm[idx] = gm; g_ps[idx] = S; g_pn[idx] = N;
            }
#pragma unroll
            for (int mt = 0; mt < 2; mt++)
#pragma unroll
                for (int nt = 0; nt < 2; nt++)
#pragma unroll
                    for (int r = 0; r < 4; r++) {
                        att1[mt][nt][r] = 0; att2[mt][nt][r] = 0;
                        tt1[mt][nt][r] = 0;  tt2[mt][nt][r] = 0;
                    }
        }
    }
}

// ---------------- reduce 64 partials per row -> logits ----------------
__global__ void __launch_bounds__(256)
reduce_kernel(const float* __restrict__ bias) {
    const int rr = blockIdx.x * 8 + (threadIdx.x >> 5);
    const int lane = threadIdx.x & 31;
    const size_t base = (size_t)rr * NLB;
    const float ma = g_pm[base + lane], mb = g_pm[base + 32 + lane];
    float gm = fmaxf(ma, mb);
#pragma unroll
    for (int s = 16; s > 0; s >>= 1) gm = fmaxf(gm, __shfl_xor_sync(0xffffffffu, gm, s));
    const float sa = __expf(ma - gm), sb2 = __expf(mb - gm);
    float S = g_ps[base + lane] * sa + g_ps[base + 32 + lane] * sb2;
    float N = g_pn[base + lane] * sa + g_pn[base + 32 + lane] * sb2;
#pragma unroll
    for (int s = 16; s > 0; s >>= 1) {
        S += __shfl_xor_sync(0xffffffffu, S, s);
        N += __shfl_xor_sync(0xffffffffu, N, s);
    }
    if (lane == 0) g_y[rr] = N / S + bias[rr & (Y_ - 1)];
}

// ---------------- cross-entropy loss (target arrives int32) --------------
__global__ void loss_kernel(const int* __restrict__ target) {
    __shared__ float sred[256];
    const int tid = threadIdx.x;
    float total = 0.f;
    for (int b = 0; b < B_; b++) {
        const float* row = g_y + (size_t)b * Y_;
        float m = -INFINITY;
        for (int i = tid; i < Y_; i += 256) m = fmaxf(m, row[i]);
        sred[tid] = m; __syncthreads();
        for (int s = 128; s > 0; s >>= 1) {
            if (tid < s) sred[tid] = fmaxf(sred[tid], sred[tid + s]);
            __syncthreads();
        }
        m = sred[0]; __syncthreads();
        float sum = 0.f;
        for (int i = tid; i < Y_; i += 256) sum += __expf(row[i] - m);
        sred[tid] = sum; __syncthreads();
        for (int s = 128; s > 0; s >>= 1) {
            if (tid < s) sred[tid] += sred[tid + s];
            __syncthreads();
        }
        if (tid == 0) total += m + logf(sred[0]) - row[target[b]];
        __syncthreads();
    }
    if (tid == 0) g_loss = total / (float)B_;
}

__global__ void writeout_kernel(float* __restrict__ out, int out_size) {
    const int idx = blockIdx.x * blockDim.x + threadIdx.x;
    const int ny = B_ * Y_;
    if (out_size >= ny + 1) {
        if (idx == 0) out[0] = g_loss;
        if (idx < ny) out[(out_size - ny) + idx] = g_y[idx];
    } else if (out_size == ny) {
        if (idx < ny) out[idx] = g_y[idx];
    } else {
        if (idx == 0 && out_size >= 1) out[0] = g_loss;
    }
}

extern "C" void kernel_launch(void* const* d_in, const int* in_sizes, int n_in,
                              void* d_out, int out_size) {
    const float* x    = (const float*)d_in[0];
    const float* U    = (const float*)d_in[1];
    const float* F    = (const float*)d_in[2];
    const float* bias = (const float*)d_in[3];
    const int*   tg   = (const int*)d_in[4];

    void *X1, *X0, *U1, *U0, *F1, *F0, *sx, *su, *sf;
    cudaGetSymbolAddress(&X1, g_X1); cudaGetSymbolAddress(&X0, g_X0);
    cudaGetSymbolAddress(&U1, g_U1); cudaGetSymbolAddress(&U0, g_U0);
    cudaGetSymbolAddress(&F1, g_F1); cudaGetSymbolAddress(&F0, g_F0);
    cudaGetSymbolAddress(&sx, g_sx); cudaGetSymbolAddress(&su, g_su);
    cudaGetSymbolAddress(&sf, g_sf);

    quant_kernel<<<B_ * L_ / 8, 256>>>(x, (int8_t*)X1, (int8_t*)X0, (float*)sx, B_ * L_);
    quant_kernel<<<Y_ / 8, 256>>>(U, (int8_t*)U1, (int8_t*)U0, (float*)su, Y_);
    quant_kernel<<<Y_ / 8, 256>>>(F, (int8_t*)F1, (int8_t*)F0, (float*)sf, Y_);

    int nsm = 148;
    cudaDeviceGetAttribute(&nsm, cudaDevAttrMultiProcessorCount, 0);
    cudaFuncSetAttribute(gemm_kernel, cudaFuncAttributeMaxDynamicSharedMemorySize, SMEM_TOT);
    gemm_kernel<<<nsm, 512, SMEM_TOT>>>();

    reduce_kernel<<<B_ * Y_ / 8, 256>>>(bias);
    loss_kernel<<<1, 256>>>(tg);
    writeout_kernel<<<(B_ * Y_ + 255) / 256, 256>>>((float*)d_out, out_size);
}

// round 11
// speedup vs baseline: 4.7479x; 4.7479x over previous
#include <cuda_runtime.h>
#include <cuda_fp16.h>
#include <math.h>
#include <stdint.h>

#define B_ 8
#define L_ 4096
#define D_ 768
#define Y_ 2048
#define NLB 32                  // l-blocks (L/128)
#define NTILES 4096             // 32 lblk * 16 yblk * 8 b

// ---------------- device scratch (no allocations allowed) ----------------
__device__ __half g_Xh[(size_t)B_ * L_ * D_];
__device__ __half g_Xl[(size_t)B_ * L_ * D_];
__device__ __half g_Uh[(size_t)Y_ * D_];
__device__ __half g_Fh[(size_t)Y_ * D_];
__device__ float g_pm[(size_t)B_ * Y_ * NLB];
__device__ float g_ps[(size_t)B_ * Y_ * NLB];
__device__ float g_pn[(size_t)B_ * Y_ * NLB];
__device__ float g_y[(size_t)B_ * Y_];
__device__ float g_loss;

// ---------------- helpers ----------------
__device__ __forceinline__ uint32_t smem_u32(const void* p) {
    uint32_t a;
    asm("{ .reg .u64 t; cvta.to.shared.u64 t, %1; cvt.u32.u64 %0, t; }" : "=r"(a) : "l"(p));
    return a;
}
#define SWZ128(x) ((x) ^ (((x) >> 3) & 0x70))

#define CP16(dst, src) \
    asm volatile("cp.async.cg.shared.global [%0], [%1], 16;" :: "r"(dst), "l"(src))
#define CPCOMMIT() asm volatile("cp.async.commit_group;" ::: "memory")
#define CPWAIT1() asm volatile("cp.async.wait_group 1;" ::: "memory")
#define CPWAIT0() asm volatile("cp.async.wait_group 0;" ::: "memory")

__device__ __forceinline__ void ldsm_x4(uint32_t* r, uint32_t addr) {
    asm volatile("ldmatrix.sync.aligned.m8n8.x4.shared.b16 {%0,%1,%2,%3}, [%4];"
        : "=r"(r[0]), "=r"(r[1]), "=r"(r[2]), "=r"(r[3]) : "r"(addr));
}
#define MMA_F16(d, a, b0, b1)                                                 \
    asm volatile("mma.sync.aligned.m16n8k16.row.col.f32.f16.f16.f32 "         \
        "{%0,%1,%2,%3}, {%4,%5,%6,%7}, {%8,%9}, {%0,%1,%2,%3};"               \
        : "+f"((d)[0]), "+f"((d)[1]), "+f"((d)[2]), "+f"((d)[3])              \
        : "r"((a)[0]), "r"((a)[1]), "r"((a)[2]), "r"((a)[3]),                 \
          "r"(b0), "r"(b1))

// ---------------- splits: fp32 -> fp16 (2-limb for x, 1-limb for U/F) -----
__global__ void split2_f16(const float* __restrict__ in,
                           __half* __restrict__ hi, __half* __restrict__ lo, int n4) {
    int i = blockIdx.x * blockDim.x + threadIdx.x;
    if (i >= n4) return;
    float4 v = ((const float4*)in)[i];
    __half h0 = __float2half_rn(v.x), h1 = __float2half_rn(v.y);
    __half h2 = __float2half_rn(v.z), h3 = __float2half_rn(v.w);
    __half l0 = __float2half_rn(v.x - __half2float(h0));
    __half l1 = __float2half_rn(v.y - __half2float(h1));
    __half l2 = __float2half_rn(v.z - __half2float(h2));
    __half l3 = __float2half_rn(v.w - __half2float(h3));
    ((__half2*)hi)[i * 2 + 0] = __half2(h0, h1);
    ((__half2*)hi)[i * 2 + 1] = __half2(h2, h3);
    ((__half2*)lo)[i * 2 + 0] = __half2(l0, l1);
    ((__half2*)lo)[i * 2 + 1] = __half2(l2, l3);
}

__global__ void split1_f16(const float* __restrict__ in,
                           __half* __restrict__ hi, int n4) {
    int i = blockIdx.x * blockDim.x + threadIdx.x;
    if (i >= n4) return;
    float4 v = ((const float4*)in)[i];
    ((__half2*)hi)[i * 2 + 0] = __half2(__float2half_rn(v.x), __float2half_rn(v.y));
    ((__half2*)hi)[i * 2 + 1] = __half2(__float2half_rn(v.z), __float2half_rn(v.w));
}

// ------- persistent dual GEMM (fp16, 4 MMA/k16) + register softmax --------
// CTA tile 128y x 128l, 512 threads, warp grid 4y x 4l (warp tile 32y x 32l).
// Stage = k-chunk 64 fp16 (128B rows): Uh,Fh,Xh,Xl tiles 16KB each = 64KB.
// 3-stage ring, ONE __syncthreads per stage (issue into buffer freed at s-1).
#define T16K 16384
#define STAGE_B 65536
#define PART_OFF (3 * STAGE_B)     // 196608
#define SMEM_TOT (PART_OFF + 3 * 128 * 4 * 4)   // 202752

__device__ __forceinline__ void issue_stage(uint32_t sb, int ls,
                                            int tid, int stride) {
    const int tl = ls / 12, ks = ls - tl * 12;
    const int t = blockIdx.x + tl * stride;
    const int lblk = t & 31, yblk = (t >> 5) & 15, b = t >> 9;
    const __half* srcs[4] = {
        g_Uh + (size_t)(yblk * 128) * D_,
        g_Fh + (size_t)(yblk * 128) * D_,
        g_Xh + ((size_t)b * L_ + lblk * 128) * D_,
        g_Xl + ((size_t)b * L_ + lblk * 128) * D_
    };
    const uint32_t bufb = (uint32_t)(ls % 3) * STAGE_B;
#pragma unroll
    for (int j = 0; j < 8; j++) {
        const int gi = j * 512 + tid;
        const int tt = gi >> 10;
        const int ci = gi & 1023;
        const int row = ci >> 3, c16 = ci & 7;
        const char* src = (const char*)(srcs[tt] + (size_t)row * D_ + ks * 64) + c16 * 16;
        const uint32_t dst = sb + bufb + tt * T16K + SWZ128(row * 128 + c16 * 16);
        CP16(dst, src);
    }
    CPCOMMIT();
}

__global__ void __launch_bounds__(512, 1)
gemm_kernel() {
    extern __shared__ char smem[];
    const uint32_t sb = smem_u32(smem);
    float* partm = (float*)(smem + PART_OFF);          // [128][4]
    float* parts = partm + 128 * 4;
    float* partn = parts + 128 * 4;

    const int tid = threadIdx.x, lane = tid & 31, wid = tid >> 5;
    const int stride = gridDim.x;
    const int myN = (NTILES - blockIdx.x + stride - 1) / stride;
    const int total = 12 * myN;

    const int my = (wid & 3) * 32;
    const int nl = (wid >> 2) * 32;
    const int wcol = wid >> 2;

    // unswizzled byte offsets; SWZ128 applied per load (swizzle not additive)
    const uint32_t aByte = (uint32_t)((my + (lane & 15)) * 128 + ((lane >> 4) << 4));
    const uint32_t bByte = (uint32_t)((nl + (lane & 7) + ((lane >> 4) & 1) * 8) * 128
                                      + (((lane >> 3) & 1) << 4));

    float att[2][4][4], tac[2][4][4];
#pragma unroll
    for (int mt = 0; mt < 2; mt++)
#pragma unroll
        for (int nt = 0; nt < 4; nt++)
#pragma unroll
            for (int r = 0; r < 4; r++) { att[mt][nt][r] = 0.f; tac[mt][nt][r] = 0.f; }

    issue_stage(sb, 0, tid, stride);
    if (total > 1) issue_stage(sb, 1, tid, stride);

    for (int ls = 0; ls < total; ls++) {
        if (ls >= total - 1) { CPWAIT0(); } else { CPWAIT1(); }
        __syncthreads();                      // all warps done with stage ls-1
        if (ls + 2 < total) issue_stage(sb, ls + 2, tid, stride);
        const uint32_t bufo = sb + (uint32_t)(ls % 3) * STAGE_B;

#pragma unroll
        for (int kk = 0; kk < 4; kk++) {
            uint32_t bh0[4], bl0[4], bh1[4], bl1[4];
            {
                const uint32_t sw0 = SWZ128(bByte + (uint32_t)(kk * 32));
                const uint32_t sw1 = SWZ128(bByte + (uint32_t)(16 * 128 + kk * 32));
                ldsm_x4(bh0, bufo + 2 * T16K + sw0);
                ldsm_x4(bl0, bufo + 3 * T16K + sw0);
                ldsm_x4(bh1, bufo + 2 * T16K + sw1);
                ldsm_x4(bl1, bufo + 3 * T16K + sw1);
            }
#pragma unroll
            for (int mt = 0; mt < 2; mt++) {
                const uint32_t swa = SWZ128(aByte + (uint32_t)(mt * 16 * 128 + kk * 32));
                uint32_t uh[4], fh[4];
                ldsm_x4(uh, bufo + 0 * T16K + swa);
                ldsm_x4(fh, bufo + 1 * T16K + swa);
                MMA_F16(att[mt][0], uh, bh0[0], bh0[1]);
                MMA_F16(att[mt][0], uh, bl0[0], bl0[1]);
                MMA_F16(att[mt][1], uh, bh0[2], bh0[3]);
                MMA_F16(att[mt][1], uh, bl0[2], bl0[3]);
                MMA_F16(att[mt][2], uh, bh1[0], bh1[1]);
                MMA_F16(att[mt][2], uh, bl1[0], bl1[1]);
                MMA_F16(att[mt][3], uh, bh1[2], bh1[3]);
                MMA_F16(att[mt][3], uh, bl1[2], bl1[3]);
                MMA_F16(tac[mt][0], fh, bh0[0], bh0[1]);
                MMA_F16(tac[mt][0], fh, bl0[0], bl0[1]);
                MMA_F16(tac[mt][1], fh, bh0[2], bh0[3]);
                MMA_F16(tac[mt][1], fh, bl0[2], bl0[3]);
                MMA_F16(tac[mt][2], fh, bh1[0], bh1[1]);
                MMA_F16(tac[mt][2], fh, bl1[0], bl1[1]);
                MMA_F16(tac[mt][3], fh, bh1[2], bh1[3]);
                MMA_F16(tac[mt][3], fh, bl1[2], bl1[3]);
            }
        }

        if ((ls % 12) == 11) {
            // ---- register-level partial softmax for this 128x128 tile ----
            const int t = blockIdx.x + (ls / 12) * stride;
            const int lblk = t & 31, yblk = (t >> 5) & 15, b = t >> 9;
#pragma unroll
            for (int mt = 0; mt < 2; mt++) {
#pragma unroll
                for (int half = 0; half < 2; half++) {
                    float a[8], tv[8];
#pragma unroll
                    for (int nt = 0; nt < 4; nt++)
#pragma unroll
                        for (int j = 0; j < 2; j++) {
                            a[nt * 2 + j] = att[mt][nt][half * 2 + j];
                            tv[nt * 2 + j] = tac[mt][nt][half * 2 + j];
                        }
                    float m = a[0];
#pragma unroll
                    for (int j = 1; j < 8; j++) m = fmaxf(m, a[j]);
                    m = fmaxf(m, __shfl_xor_sync(0xffffffffu, m, 1));
                    m = fmaxf(m, __shfl_xor_sync(0xffffffffu, m, 2));
                    float S = 0.f, N = 0.f;
#pragma unroll
                    for (int j = 0; j < 8; j++) {
                        const float e = __expf(a[j] - m);
                        S += e;
                        N += e * tv[j];
                    }
                    S += __shfl_xor_sync(0xffffffffu, S, 1);
                    S += __shfl_xor_sync(0xffffffffu, S, 2);
                    N += __shfl_xor_sync(0xffffffffu, N, 1);
                    N += __shfl_xor_sync(0xffffffffu, N, 2);
                    if ((lane & 3) == 0) {
                        const int row = my + mt * 16 + half * 8 + (lane >> 2);
                        partm[row * 4 + wcol] = m;
                        parts[row * 4 + wcol] = S;
                        partn[row * 4 + wcol] = N;
                    }
                }
            }
            __syncthreads();
            if (tid < 128) {
                const float m0 = partm[tid * 4 + 0], m1 = partm[tid * 4 + 1];
                const float m2 = partm[tid * 4 + 2], m3 = partm[tid * 4 + 3];
                const float gm = fmaxf(fmaxf(m0, m1), fmaxf(m2, m3));
                const float e0 = __expf(m0 - gm), e1 = __expf(m1 - gm);
                const float e2 = __expf(m2 - gm), e3 = __expf(m3 - gm);
                const float S = parts[tid * 4 + 0] * e0 + parts[tid * 4 + 1] * e1
                              + parts[tid * 4 + 2] * e2 + parts[tid * 4 + 3] * e3;
                const float N = partn[tid * 4 + 0] * e0 + partn[tid * 4 + 1] * e1
                              + partn[tid * 4 + 2] * e2 + partn[tid * 4 + 3] * e3;
                const size_t idx = ((size_t)b * Y_ + yblk * 128 + tid) * NLB + lblk;
                g_pm[idx] = gm; g_ps[idx] = S; g_pn[idx] = N;
            }
#pragma unroll
            for (int mt = 0; mt < 2; mt++)
#pragma unroll
                for (int nt = 0; nt < 4; nt++)
#pragma unroll
                    for (int r = 0; r < 4; r++) {
                        att[mt][nt][r] = 0.f; tac[mt][nt][r] = 0.f;
                    }
        }
    }
}

// ---------------- reduce 32 partials per row -> logits ----------------
__global__ void __launch_bounds__(256)
reduce_kernel(const float* __restrict__ bias) {
    const int rr = blockIdx.x * 8 + (threadIdx.x >> 5);
    const int lane = threadIdx.x & 31;
    const size_t base = (size_t)rr * NLB + lane;
    const float m = g_pm[base];
    float gm = m;
#pragma unroll
    for (int s = 16; s > 0; s >>= 1) gm = fmaxf(gm, __shfl_xor_sync(0xffffffffu, gm, s));
    const float sc = __expf(m - gm);
    float S = g_ps[base] * sc;
    float N = g_pn[base] * sc;
#pragma unroll
    for (int s = 16; s > 0; s >>= 1) {
        S += __shfl_xor_sync(0xffffffffu, S, s);
        N += __shfl_xor_sync(0xffffffffu, N, s);
    }
    if (lane == 0) g_y[rr] = N / S + bias[rr & (Y_ - 1)];
}

// ---------------- cross-entropy loss (target arrives int32) --------------
__global__ void loss_kernel(const int* __restrict__ target) {
    __shared__ float sred[256];
    const int tid = threadIdx.x;
    float total = 0.f;
    for (int b = 0; b < B_; b++) {
        const float* row = g_y + (size_t)b * Y_;
        float m = -INFINITY;
        for (int i = tid; i < Y_; i += 256) m = fmaxf(m, row[i]);
        sred[tid] = m; __syncthreads();
        for (int s = 128; s > 0; s >>= 1) {
            if (tid < s) sred[tid] = fmaxf(sred[tid], sred[tid + s]);
            __syncthreads();
        }
        m = sred[0]; __syncthreads();
        float sum = 0.f;
        for (int i = tid; i < Y_; i += 256) sum += __expf(row[i] - m);
        sred[tid] = sum; __syncthreads();
        for (int s = 128; s > 0; s >>= 1) {
            if (tid < s) sred[tid] += sred[tid + s];
            __syncthreads();
        }
        if (tid == 0) total += m + logf(sred[0]) - row[target[b]];
        __syncthreads();
    }
    if (tid == 0) g_loss = total / (float)B_;
}

__global__ void writeout_kernel(float* __restrict__ out, int out_size) {
    const int idx = blockIdx.x * blockDim.x + threadIdx.x;
    const int ny = B_ * Y_;
    if (out_size >= ny + 1) {
        if (idx == 0) out[0] = g_loss;
        if (idx < ny) out[(out_size - ny) + idx] = g_y[idx];
    } else if (out_size == ny) {
        if (idx < ny) out[idx] = g_y[idx];
    } else {
        if (idx == 0 && out_size >= 1) out[0] = g_loss;
    }
}

extern "C" void kernel_launch(void* const* d_in, const int* in_sizes, int n_in,
                              void* d_out, int out_size) {
    const float* x    = (const float*)d_in[0];
    const float* U    = (const float*)d_in[1];
    const float* F    = (const float*)d_in[2];
    const float* bias = (const float*)d_in[3];
    const int*   tg   = (const int*)d_in[4];

    void *Xh, *Xl, *Uh, *Fh;
    cudaGetSymbolAddress(&Xh, g_Xh); cudaGetSymbolAddress(&Xl, g_Xl);
    cudaGetSymbolAddress(&Uh, g_Uh); cudaGetSymbolAddress(&Fh, g_Fh);

    const int nx4 = B_ * L_ * D_ / 4;
    const int nw4 = Y_ * D_ / 4;
    split2_f16<<<(nx4 + 255) / 256, 256>>>(x, (__half*)Xh, (__half*)Xl, nx4);
    split1_f16<<<(nw4 + 255) / 256, 256>>>(U, (__half*)Uh, nw4);
    split1_f16<<<(nw4 + 255) / 256, 256>>>(F, (__half*)Fh, nw4);

    int nsm = 148;
    cudaDeviceGetAttribute(&nsm, cudaDevAttrMultiProcessorCount, 0);
    cudaFuncSetAttribute(gemm_kernel, cudaFuncAttributeMaxDynamicSharedMemorySize, SMEM_TOT);
    gemm_kernel<<<nsm, 512, SMEM_TOT>>>();

    reduce_kernel<<<B_ * Y_ / 8, 256>>>(bias);
    loss_kernel<<<1, 256>>>(tg);
    writeout_kernel<<<(B_ * Y_ + 255) / 256, 256>>>((float*)d_out, out_size);
}

// round 12
// speedup vs baseline: 7.7473x; 1.6317x over previous
#include <cuda_runtime.h>
#include <cuda_fp16.h>
#include <math.h>
#include <stdint.h>

#define B_ 8
#define L_ 4096
#define D_ 768
#define Y_ 2048
#define NLB 32                  // l-blocks (L/128)
#define NTILES 4096             // 32 lblk * 16 yblk * 8 b

// ---------------- device scratch (no allocations allowed) ----------------
__device__ __half g_Xh[(size_t)B_ * L_ * D_];
__device__ __half g_Uh[(size_t)Y_ * D_];
__device__ __half g_Fh[(size_t)Y_ * D_];
__device__ float g_pm[(size_t)B_ * Y_ * NLB];
__device__ float g_ps[(size_t)B_ * Y_ * NLB];
__device__ float g_pn[(size_t)B_ * Y_ * NLB];
__device__ float g_y[(size_t)B_ * Y_];
__device__ float g_loss;

// ---------------- helpers ----------------
__device__ __forceinline__ uint32_t smem_u32(const void* p) {
    uint32_t a;
    asm("{ .reg .u64 t; cvta.to.shared.u64 t, %1; cvt.u32.u64 %0, t; }" : "=r"(a) : "l"(p));
    return a;
}
#define SWZ128(x) ((x) ^ (((x) >> 3) & 0x70))

#define CP16(dst, src) \
    asm volatile("cp.async.cg.shared.global [%0], [%1], 16;" :: "r"(dst), "l"(src))
#define CPCOMMIT() asm volatile("cp.async.commit_group;" ::: "memory")
#define CPWAIT2() asm volatile("cp.async.wait_group 2;" ::: "memory")
#define CPWAIT1() asm volatile("cp.async.wait_group 1;" ::: "memory")
#define CPWAIT0() asm volatile("cp.async.wait_group 0;" ::: "memory")

__device__ __forceinline__ void ldsm_x4(uint32_t* r, uint32_t addr) {
    asm volatile("ldmatrix.sync.aligned.m8n8.x4.shared.b16 {%0,%1,%2,%3}, [%4];"
        : "=r"(r[0]), "=r"(r[1]), "=r"(r[2]), "=r"(r[3]) : "r"(addr));
}
#define MMA_F16(d, a, b0, b1)                                                 \
    asm volatile("mma.sync.aligned.m16n8k16.row.col.f32.f16.f16.f32 "         \
        "{%0,%1,%2,%3}, {%4,%5,%6,%7}, {%8,%9}, {%0,%1,%2,%3};"               \
        : "+f"((d)[0]), "+f"((d)[1]), "+f"((d)[2]), "+f"((d)[3])              \
        : "r"((a)[0]), "r"((a)[1]), "r"((a)[2]), "r"((a)[3]),                 \
          "r"(b0), "r"(b1))

// ---------------- fp32 -> fp16 convert ----------------
__global__ void cvt_f16(const float* __restrict__ in, __half* __restrict__ out, int n4) {
    int i = blockIdx.x * blockDim.x + threadIdx.x;
    if (i >= n4) return;
    float4 v = ((const float4*)in)[i];
    ((__half2*)out)[i * 2 + 0] = __half2(__float2half_rn(v.x), __float2half_rn(v.y));
    ((__half2*)out)[i * 2 + 1] = __half2(__float2half_rn(v.z), __float2half_rn(v.w));
}

// ------- persistent dual GEMM (pure fp16, 2 MMA/k16) + register softmax ----
// CTA tile 128y x 128l, 512 threads, warp grid 4y x 4l (warp tile 32y x 32l).
// Stage = k-chunk 64 fp16 (128B rows): Uh, Fh, Xh tiles 16KB each = 48KB.
// 4-stage ring, prefetch depth 3, ONE __syncthreads per stage.
#define T16K 16384
#define STAGE_B 49152
#define PART_OFF (4 * STAGE_B)     // 196608
#define SMEM_TOT (PART_OFF + 3 * 128 * 4 * 4)   // 202752

__device__ __forceinline__ void issue_stage(uint32_t sb, int ls,
                                            int tid, int stride) {
    const int tl = ls / 12, ks = ls - tl * 12;
    const int t = blockIdx.x + tl * stride;
    const int lblk = t & 31, yblk = (t >> 5) & 15, b = t >> 9;
    const __half* srcs[3] = {
        g_Uh + (size_t)(yblk * 128) * D_,
        g_Fh + (size_t)(yblk * 128) * D_,
        g_Xh + ((size_t)b * L_ + lblk * 128) * D_
    };
    const uint32_t bufb = (uint32_t)(ls & 3) * STAGE_B;
#pragma unroll
    for (int j = 0; j < 6; j++) {
        const int gi = j * 512 + tid;          // 0..3071
        const int tt = gi >> 10;               // tile 0..2
        const int ci = gi & 1023;
        const int row = ci >> 3, c16 = ci & 7;
        const char* src = (const char*)(srcs[tt] + (size_t)row * D_ + ks * 64) + c16 * 16;
        const uint32_t dst = sb + bufb + tt * T16K + SWZ128(row * 128 + c16 * 16);
        CP16(dst, src);
    }
    CPCOMMIT();
}

__global__ void __launch_bounds__(512, 1)
gemm_kernel() {
    extern __shared__ char smem[];
    const uint32_t sb = smem_u32(smem);
    float* partm = (float*)(smem + PART_OFF);          // [128][4]
    float* parts = partm + 128 * 4;
    float* partn = parts + 128 * 4;

    const int tid = threadIdx.x, lane = tid & 31, wid = tid >> 5;
    const int stride = gridDim.x;
    const int myN = (NTILES - blockIdx.x + stride - 1) / stride;
    const int total = 12 * myN;

    const int my = (wid & 3) * 32;
    const int nl = (wid >> 2) * 32;
    const int wcol = wid >> 2;

    // unswizzled byte offsets; SWZ128 applied per load (swizzle not additive)
    const uint32_t aByte = (uint32_t)((my + (lane & 15)) * 128 + ((lane >> 4) << 4));
    const uint32_t bByte = (uint32_t)((nl + (lane & 7) + ((lane >> 4) & 1) * 8) * 128
                                      + (((lane >> 3) & 1) << 4));

    float att[2][4][4], tac[2][4][4];
#pragma unroll
    for (int mt = 0; mt < 2; mt++)
#pragma unroll
        for (int nt = 0; nt < 4; nt++)
#pragma unroll
            for (int r = 0; r < 4; r++) { att[mt][nt][r] = 0.f; tac[mt][nt][r] = 0.f; }

    issue_stage(sb, 0, tid, stride);
    if (total > 1) issue_stage(sb, 1, tid, stride);
    if (total > 2) issue_stage(sb, 2, tid, stride);

    for (int ls = 0; ls < total; ls++) {
        const int rem = total - ls - 1;
        if (rem >= 2) { CPWAIT2(); } else if (rem == 1) { CPWAIT1(); } else { CPWAIT0(); }
        __syncthreads();                      // all warps done with stage ls-1's buffer
        if (ls + 3 < total) issue_stage(sb, ls + 3, tid, stride);
        const uint32_t bufo = sb + (uint32_t)(ls & 3) * STAGE_B;

#pragma unroll
        for (int kk = 0; kk < 4; kk++) {
            uint32_t bh0[4], bh1[4];
            {
                const uint32_t sw0 = SWZ128(bByte + (uint32_t)(kk * 32));
                const uint32_t sw1 = SWZ128(bByte + (uint32_t)(16 * 128 + kk * 32));
                ldsm_x4(bh0, bufo + 2 * T16K + sw0);
                ldsm_x4(bh1, bufo + 2 * T16K + sw1);
            }
#pragma unroll
            for (int mt = 0; mt < 2; mt++) {
                const uint32_t swa = SWZ128(aByte + (uint32_t)(mt * 16 * 128 + kk * 32));
                uint32_t uh[4], fh[4];
                ldsm_x4(uh, bufo + 0 * T16K + swa);
                ldsm_x4(fh, bufo + 1 * T16K + swa);
                MMA_F16(att[mt][0], uh, bh0[0], bh0[1]);
                MMA_F16(att[mt][1], uh, bh0[2], bh0[3]);
                MMA_F16(att[mt][2], uh, bh1[0], bh1[1]);
                MMA_F16(att[mt][3], uh, bh1[2], bh1[3]);
                MMA_F16(tac[mt][0], fh, bh0[0], bh0[1]);
                MMA_F16(tac[mt][1], fh, bh0[2], bh0[3]);
                MMA_F16(tac[mt][2], fh, bh1[0], bh1[1]);
                MMA_F16(tac[mt][3], fh, bh1[2], bh1[3]);
            }
        }

        if ((ls % 12) == 11) {
            // ---- register-level partial softmax for this 128x128 tile ----
            const int t = blockIdx.x + (ls / 12) * stride;
            const int lblk = t & 31, yblk = (t >> 5) & 15, b = t >> 9;
#pragma unroll
            for (int mt = 0; mt < 2; mt++) {
#pragma unroll
                for (int half = 0; half < 2; half++) {
                    float a[8], tv[8];
#pragma unroll
                    for (int nt = 0; nt < 4; nt++)
#pragma unroll
                        for (int j = 0; j < 2; j++) {
                            a[nt * 2 + j] = att[mt][nt][half * 2 + j];
                            tv[nt * 2 + j] = tac[mt][nt][half * 2 + j];
                        }
                    float m = a[0];
#pragma unroll
                    for (int j = 1; j < 8; j++) m = fmaxf(m, a[j]);
                    m = fmaxf(m, __shfl_xor_sync(0xffffffffu, m, 1));
                    m = fmaxf(m, __shfl_xor_sync(0xffffffffu, m, 2));
                    float S = 0.f, N = 0.f;
#pragma unroll
                    for (int j = 0; j < 8; j++) {
                        const float e = __expf(a[j] - m);
                        S += e;
                        N += e * tv[j];
                    }
                    S += __shfl_xor_sync(0xffffffffu, S, 1);
                    S += __shfl_xor_sync(0xffffffffu, S, 2);
                    N += __shfl_xor_sync(0xffffffffu, N, 1);
                    N += __shfl_xor_sync(0xffffffffu, N, 2);
                    if ((lane & 3) == 0) {
                        const int row = my + mt * 16 + half * 8 + (lane >> 2);
                        partm[row * 4 + wcol] = m;
                        parts[row * 4 + wcol] = S;
                        partn[row * 4 + wcol] = N;
                    }
                }
            }
            __syncthreads();
            if (tid < 128) {
                const float m0 = partm[tid * 4 + 0], m1 = partm[tid * 4 + 1];
                const float m2 = partm[tid * 4 + 2], m3 = partm[tid * 4 + 3];
                const float gm = fmaxf(fmaxf(m0, m1), fmaxf(m2, m3));
                const float e0 = __expf(m0 - gm), e1 = __expf(m1 - gm);
                const float e2 = __expf(m2 - gm), e3 = __expf(m3 - gm);
                const float S = parts[tid * 4 + 0] * e0 + parts[tid * 4 + 1] * e1
                              + parts[tid * 4 + 2] * e2 + parts[tid * 4 + 3] * e3;
                const float N = partn[tid * 4 + 0] * e0 + partn[tid * 4 + 1] * e1
                              + partn[tid * 4 + 2] * e2 + partn[tid * 4 + 3] * e3;
                const size_t idx = ((size_t)b * Y_ + yblk * 128 + tid) * NLB + lblk;
                g_pm[idx] = gm; g_ps[idx] = S; g_pn[idx] = N;
            }
#pragma unroll
            for (int mt = 0; mt < 2; mt++)
#pragma unroll
                for (int nt = 0; nt < 4; nt++)
#pragma unroll
                    for (int r = 0; r < 4; r++) {
                        att[mt][nt][r] = 0.f; tac[mt][nt][r] = 0.f;
                    }
        }
    }
}

// ---------------- reduce 32 partials per row -> logits ----------------
__global__ void __launch_bounds__(256)
reduce_kernel(const float* __restrict__ bias) {
    const int rr = blockIdx.x * 8 + (threadIdx.x >> 5);
    const int lane = threadIdx.x & 31;
    const size_t base = (size_t)rr * NLB + lane;
    const float m = g_pm[base];
    float gm = m;
#pragma unroll
    for (int s = 16; s > 0; s >>= 1) gm = fmaxf(gm, __shfl_xor_sync(0xffffffffu, gm, s));
    const float sc = __expf(m - gm);
    float S = g_ps[base] * sc;
    float N = g_pn[base] * sc;
#pragma unroll
    for (int s = 16; s > 0; s >>= 1) {
        S += __shfl_xor_sync(0xffffffffu, S, s);
        N += __shfl_xor_sync(0xffffffffu, N, s);
    }
    if (lane == 0) g_y[rr] = N / S + bias[rr & (Y_ - 1)];
}

// ---------------- cross-entropy loss (target arrives int32) --------------
__global__ void loss_kernel(const int* __restrict__ target) {
    __shared__ float sred[256];
    const int tid = threadIdx.x;
    float total = 0.f;
    for (int b = 0; b < B_; b++) {
        const float* row = g_y + (size_t)b * Y_;
        float m = -INFINITY;
        for (int i = tid; i < Y_; i += 256) m = fmaxf(m, row[i]);
        sred[tid] = m; __syncthreads();
        for (int s = 128; s > 0; s >>= 1) {
            if (tid < s) sred[tid] = fmaxf(sred[tid], sred[tid + s]);
            __syncthreads();
        }
        m = sred[0]; __syncthreads();
        float sum = 0.f;
        for (int i = tid; i < Y_; i += 256) sum += __expf(row[i] - m);
        sred[tid] = sum; __syncthreads();
        for (int s = 128; s > 0; s >>= 1) {
            if (tid < s) sred[tid] += sred[tid + s];
            __syncthreads();
        }
        if (tid == 0) total += m + logf(sred[0]) - row[target[b]];
        __syncthreads();
    }
    if (tid == 0) g_loss = total / (float)B_;
}

__global__ void writeout_kernel(float* __restrict__ out, int out_size) {
    const int idx = blockIdx.x * blockDim.x + threadIdx.x;
    const int ny = B_ * Y_;
    if (out_size >= ny + 1) {
        if (idx == 0) out[0] = g_loss;
        if (idx < ny) out[(out_size - ny) + idx] = g_y[idx];
    } else if (out_size == ny) {
        if (idx < ny) out[idx] = g_y[idx];
    } else {
        if (idx == 0 && out_size >= 1) out[0] = g_loss;
    }
}

extern "C" void kernel_launch(void* const* d_in, const int* in_sizes, int n_in,
                              void* d_out, int out_size) {
    const float* x    = (const float*)d_in[0];
    const float* U    = (const float*)d_in[1];
    const float* F    = (const float*)d_in[2];
    const float* bias = (const float*)d_in[3];
    const int*   tg   = (const int*)d_in[4];

    void *Xh, *Uh, *Fh;
    cudaGetSymbolAddress(&Xh, g_Xh);
    cudaGetSymbolAddress(&Uh, g_Uh);
    cudaGetSymbolAddress(&Fh, g_Fh);

    const int nx4 = B_ * L_ * D_ / 4;
    const int nw4 = Y_ * D_ / 4;
    cvt_f16<<<(nx4 + 255) / 256, 256>>>(x, (__half*)Xh, nx4);
    cvt_f16<<<(nw4 + 255) / 256, 256>>>(U, (__half*)Uh, nw4);
    cvt_f16<<<(nw4 + 255) / 256, 256>>>(F, (__half*)Fh, nw4);

    int nsm = 148;
    cudaDeviceGetAttribute(&nsm, cudaDevAttrMultiProcessorCount, 0);
    cudaFuncSetAttribute(gemm_kernel, cudaFuncAttributeMaxDynamicSharedMemorySize, SMEM_TOT);
    gemm_kernel<<<nsm, 512, SMEM_TOT>>>();

    reduce_kernel<<<B_ * Y_ / 8, 256>>>(bias);
    loss_kernel<<<1, 256>>>(tg);
    writeout_kernel<<<(B_ * Y_ + 255) / 256, 256>>>((float*)d_out, out_size);
}

// round 13
// speedup vs baseline: 7.9446x; 1.0255x over previous
#include <cuda_runtime.h>
#include <cuda_fp16.h>
#include <math.h>
#include <stdint.h>

#define B_ 8
#define L_ 4096
#define D_ 768
#define Y_ 2048
#define NLB 32                  // l-blocks (L/128)
#define NTILES 4096             // 32 lblk * 16 yblk * 8 b

// ---------------- device scratch (no allocations allowed) ----------------
__device__ __half g_Xh[(size_t)B_ * L_ * D_];
__device__ __half g_Uh[(size_t)Y_ * D_];
__device__ __half g_Fh[(size_t)Y_ * D_];
__device__ float g_pm[(size_t)B_ * Y_ * NLB];
__device__ float g_ps[(size_t)B_ * Y_ * NLB];
__device__ float g_pn[(size_t)B_ * Y_ * NLB];
__device__ float g_y[(size_t)B_ * Y_];
__device__ float g_loss;

// ---------------- helpers ----------------
__device__ __forceinline__ uint32_t smem_u32(const void* p) {
    uint32_t a;
    asm("{ .reg .u64 t; cvta.to.shared.u64 t, %1; cvt.u32.u64 %0, t; }" : "=r"(a) : "l"(p));
    return a;
}
#define SWZ128(x) ((x) ^ (((x) >> 3) & 0x70))

#define CP16(dst, src) \
    asm volatile("cp.async.cg.shared.global [%0], [%1], 16;" :: "r"(dst), "l"(src))
#define CPCOMMIT() asm volatile("cp.async.commit_group;" ::: "memory")
#define CPWAIT1() asm volatile("cp.async.wait_group 1;" ::: "memory")
#define CPWAIT0() asm volatile("cp.async.wait_group 0;" ::: "memory")

__device__ __forceinline__ void ldsm_x4(uint32_t* r, uint32_t addr) {
    asm volatile("ldmatrix.sync.aligned.m8n8.x4.shared.b16 {%0,%1,%2,%3}, [%4];"
        : "=r"(r[0]), "=r"(r[1]), "=r"(r[2]), "=r"(r[3]) : "r"(addr));
}
#define MMA_F16(d, a, b0, b1)                                                 \
    asm volatile("mma.sync.aligned.m16n8k16.row.col.f32.f16.f16.f32 "         \
        "{%0,%1,%2,%3}, {%4,%5,%6,%7}, {%8,%9}, {%0,%1,%2,%3};"               \
        : "+f"((d)[0]), "+f"((d)[1]), "+f"((d)[2]), "+f"((d)[3])              \
        : "r"((a)[0]), "r"((a)[1]), "r"((a)[2]), "r"((a)[3]),                 \
          "r"(b0), "r"(b1))

// ---------------- fp32 -> fp16 convert ----------------
__global__ void cvt_f16(const float* __restrict__ in, __half* __restrict__ out, int n4) {
    int i = blockIdx.x * blockDim.x + threadIdx.x;
    if (i >= n4) return;
    float4 v = ((const float4*)in)[i];
    ((__half2*)out)[i * 2 + 0] = __half2(__float2half_rn(v.x), __float2half_rn(v.y));
    ((__half2*)out)[i * 2 + 1] = __half2(__float2half_rn(v.z), __float2half_rn(v.w));
}

// ------- persistent dual GEMM (pure fp16, 2 MMA/k16) + register softmax ----
// CTA tile 128y x 128l, 512 threads, warp grid 4y x 4l (warp tile 32y x 32l).
// Stage = k-chunk 128 as two 64-col sub-tiles per operand:
//   tiles [U0,U1,F0,F1,X0,X1], 16KB each = 96KB/stage. 2-stage ring.
#define T16K 16384
#define STAGE_B 98304
#define PART_OFF (2 * STAGE_B)     // 196608
#define SMEM_TOT (PART_OFF + 3 * 128 * 4 * 4)   // 202752

__device__ __forceinline__ void issue_stage(uint32_t sb, int ls,
                                            int tid, int stride) {
    const int tl = ls / 6, ks = ls - tl * 6;
    const int t = blockIdx.x + tl * stride;
    const int lblk = t & 31, yblk = (t >> 5) & 15, b = t >> 9;
    const __half* srcs[3] = {
        g_Uh + (size_t)(yblk * 128) * D_,
        g_Fh + (size_t)(yblk * 128) * D_,
        g_Xh + ((size_t)b * L_ + lblk * 128) * D_
    };
    const uint32_t bufb = (uint32_t)(ls & 1) * STAGE_B;
#pragma unroll
    for (int j = 0; j < 12; j++) {
        const int gi = j * 512 + tid;          // 0..6143
        const int tt = gi >> 10;               // sub-tile 0..5
        const int ci = gi & 1023;
        const int row = ci >> 3, c16 = ci & 7;
        const __half* base = srcs[tt >> 1] + (size_t)row * D_ + ks * 128 + (tt & 1) * 64;
        const char* src = (const char*)base + c16 * 16;
        const uint32_t dst = sb + bufb + tt * T16K + SWZ128(row * 128 + c16 * 16);
        CP16(dst, src);
    }
    CPCOMMIT();
}

__global__ void __launch_bounds__(512, 1)
gemm_kernel() {
    extern __shared__ char smem[];
    const uint32_t sb = smem_u32(smem);
    float* partm = (float*)(smem + PART_OFF);          // [128][4]
    float* parts = partm + 128 * 4;
    float* partn = parts + 128 * 4;

    const int tid = threadIdx.x, lane = tid & 31, wid = tid >> 5;
    const int stride = gridDim.x;
    const int myN = (NTILES - blockIdx.x + stride - 1) / stride;
    const int total = 6 * myN;

    const int my = (wid & 3) * 32;
    const int nl = (wid >> 2) * 32;
    const int wcol = wid >> 2;

    // unswizzled byte offsets; SWZ128 applied per load (swizzle not additive)
    const uint32_t aByte = (uint32_t)((my + (lane & 15)) * 128 + ((lane >> 4) << 4));
    const uint32_t bByte = (uint32_t)((nl + (lane & 7) + ((lane >> 4) & 1) * 8) * 128
                                      + (((lane >> 3) & 1) << 4));

    float att[2][4][4], tac[2][4][4];
#pragma unroll
    for (int mt = 0; mt < 2; mt++)
#pragma unroll
        for (int nt = 0; nt < 4; nt++)
#pragma unroll
            for (int r = 0; r < 4; r++) { att[mt][nt][r] = 0.f; tac[mt][nt][r] = 0.f; }

    issue_stage(sb, 0, tid, stride);
    if (total > 1) issue_stage(sb, 1, tid, stride);

    for (int ls = 0; ls < total; ls++) {
        if (ls == total - 1) { CPWAIT0(); } else { CPWAIT1(); }
        __syncthreads();
        const uint32_t bufo = sb + (uint32_t)(ls & 1) * STAGE_B;

#pragma unroll
        for (int kk = 0; kk < 8; kk++) {
            const uint32_t hoff = (uint32_t)(kk >> 2) * T16K;
            const uint32_t kq32 = (uint32_t)((kk & 3) * 32);
            uint32_t bh0[4], bh1[4];
            {
                const uint32_t sw0 = SWZ128(bByte + kq32);
                const uint32_t sw1 = SWZ128(bByte + (uint32_t)(16 * 128) + kq32);
                ldsm_x4(bh0, bufo + 4 * T16K + hoff + sw0);
                ldsm_x4(bh1, bufo + 4 * T16K + hoff + sw1);
            }
#pragma unroll
            for (int mt = 0; mt < 2; mt++) {
                const uint32_t swa = SWZ128(aByte + (uint32_t)(mt * 16 * 128) + kq32);
                uint32_t uh[4], fh[4];
                ldsm_x4(uh, bufo + 0 * T16K + hoff + swa);
                ldsm_x4(fh, bufo + 2 * T16K + hoff + swa);
                MMA_F16(att[mt][0], uh, bh0[0], bh0[1]);
                MMA_F16(att[mt][1], uh, bh0[2], bh0[3]);
                MMA_F16(att[mt][2], uh, bh1[0], bh1[1]);
                MMA_F16(att[mt][3], uh, bh1[2], bh1[3]);
                MMA_F16(tac[mt][0], fh, bh0[0], bh0[1]);
                MMA_F16(tac[mt][1], fh, bh0[2], bh0[3]);
                MMA_F16(tac[mt][2], fh, bh1[0], bh1[1]);
                MMA_F16(tac[mt][3], fh, bh1[2], bh1[3]);
            }
        }
        __syncthreads();
        if (ls + 2 < total) issue_stage(sb, ls + 2, tid, stride);

        if ((ls % 6) == 5) {
            // ---- register-level partial softmax for this 128x128 tile ----
            const int t = blockIdx.x + (ls / 6) * stride;
            const int lblk = t & 31, yblk = (t >> 5) & 15, b = t >> 9;
#pragma unroll
            for (int mt = 0; mt < 2; mt++) {
#pragma unroll
                for (int half = 0; half < 2; half++) {
                    float a[8], tv[8];
#pragma unroll
                    for (int nt = 0; nt < 4; nt++)
#pragma unroll
                        for (int j = 0; j < 2; j++) {
                            a[nt * 2 + j] = att[mt][nt][half * 2 + j];
                            tv[nt * 2 + j] = tac[mt][nt][half * 2 + j];
                        }
                    float m = a[0];
#pragma unroll
                    for (int j = 1; j < 8; j++) m = fmaxf(m, a[j]);
                    m = fmaxf(m, __shfl_xor_sync(0xffffffffu, m, 1));
                    m = fmaxf(m, __shfl_xor_sync(0xffffffffu, m, 2));
                    float S = 0.f, N = 0.f;
#pragma unroll
                    for (int j = 0; j < 8; j++) {
                        const float e = __expf(a[j] - m);
                        S += e;
                        N += e * tv[j];
                    }
                    S += __shfl_xor_sync(0xffffffffu, S, 1);
                    S += __shfl_xor_sync(0xffffffffu, S, 2);
                    N += __shfl_xor_sync(0xffffffffu, N, 1);
                    N += __shfl_xor_sync(0xffffffffu, N, 2);
                    if ((lane & 3) == 0) {
                        const int row = my + mt * 16 + half * 8 + (lane >> 2);
                        partm[row * 4 + wcol] = m;
                        parts[row * 4 + wcol] = S;
                        partn[row * 4 + wcol] = N;
                    }
                }
            }
            __syncthreads();
            if (tid < 128) {
                const float m0 = partm[tid * 4 + 0], m1 = partm[tid * 4 + 1];
                const float m2 = partm[tid * 4 + 2], m3 = partm[tid * 4 + 3];
                const float gm = fmaxf(fmaxf(m0, m1), fmaxf(m2, m3));
                const float e0 = __expf(m0 - gm), e1 = __expf(m1 - gm);
                const float e2 = __expf(m2 - gm), e3 = __expf(m3 - gm);
                const float S = parts[tid * 4 + 0] * e0 + parts[tid * 4 + 1] * e1
                              + parts[tid * 4 + 2] * e2 + parts[tid * 4 + 3] * e3;
                const float N = partn[tid * 4 + 0] * e0 + partn[tid * 4 + 1] * e1
                              + partn[tid * 4 + 2] * e2 + partn[tid * 4 + 3] * e3;
                const size_t idx = ((size_t)b * Y_ + yblk * 128 + tid) * NLB + lblk;
                g_pm[idx] = gm; g_ps[idx] = S; g_pn[idx] = N;
            }
#pragma unroll
            for (int mt = 0; mt < 2; mt++)
#pragma unroll
                for (int nt = 0; nt < 4; nt++)
#pragma unroll
                    for (int r = 0; r < 4; r++) {
                        att[mt][nt][r] = 0.f; tac[mt][nt][r] = 0.f;
                    }
        }
    }
}

// ---------------- reduce 32 partials per row -> logits ----------------
__global__ void __launch_bounds__(256)
reduce_kernel(const float* __restrict__ bias) {
    const int rr = blockIdx.x * 8 + (threadIdx.x >> 5);
    const int lane = threadIdx.x & 31;
    const size_t base = (size_t)rr * NLB + lane;
    const float m = g_pm[base];
    float gm = m;
#pragma unroll
    for (int s = 16; s > 0; s >>= 1) gm = fmaxf(gm, __shfl_xor_sync(0xffffffffu, gm, s));
    const float sc = __expf(m - gm);
    float S = g_ps[base] * sc;
    float N = g_pn[base] * sc;
#pragma unroll
    for (int s = 16; s > 0; s >>= 1) {
        S += __shfl_xor_sync(0xffffffffu, S, s);
        N += __shfl_xor_sync(0xffffffffu, N, s);
    }
    if (lane == 0) g_y[rr] = N / S + bias[rr & (Y_ - 1)];
}

// ---------------- cross-entropy loss (target arrives int32) --------------
__global__ void loss_kernel(const int* __restrict__ target) {
    __shared__ float sred[256];
    const int tid = threadIdx.x;
    float total = 0.f;
    for (int b = 0; b < B_; b++) {
        const float* row = g_y + (size_t)b * Y_;
        float m = -INFINITY;
        for (int i = tid; i < Y_; i += 256) m = fmaxf(m, row[i]);
        sred[tid] = m; __syncthreads();
        for (int s = 128; s > 0; s >>= 1) {
            if (tid < s) sred[tid] = fmaxf(sred[tid], sred[tid + s]);
            __syncthreads();
        }
        m = sred[0]; __syncthreads();
        float sum = 0.f;
        for (int i = tid; i < Y_; i += 256) sum += __expf(row[i] - m);
        sred[tid] = sum; __syncthreads();
        for (int s = 128; s > 0; s >>= 1) {
            if (tid < s) sred[tid] += sred[tid + s];
            __syncthreads();
        }
        if (tid == 0) total += m + logf(sred[0]) - row[target[b]];
        __syncthreads();
    }
    if (tid == 0) g_loss = total / (float)B_;
}

__global__ void writeout_kernel(float* __restrict__ out, int out_size) {
    const int idx = blockIdx.x * blockDim.x + threadIdx.x;
    const int ny = B_ * Y_;
    if (out_size >= ny + 1) {
        if (idx == 0) out[0] = g_loss;
        if (idx < ny) out[(out_size - ny) + idx] = g_y[idx];
    } else if (out_size == ny) {
        if (idx < ny) out[idx] = g_y[idx];
    } else {
        if (idx == 0 && out_size >= 1) out[0] = g_loss;
    }
}

extern "C" void kernel_launch(void* const* d_in, const int* in_sizes, int n_in,
                              void* d_out, int out_size) {
    const float* x    = (const float*)d_in[0];
    const float* U    = (const float*)d_in[1];
    const float* F    = (const float*)d_in[2];
    const float* bias = (const float*)d_in[3];
    const int*   tg   = (const int*)d_in[4];

    void *Xh, *Uh, *Fh;
    cudaGetSymbolAddress(&Xh, g_Xh);
    cudaGetSymbolAddress(&Uh, g_Uh);
    cudaGetSymbolAddress(&Fh, g_Fh);

    const int nx4 = B_ * L_ * D_ / 4;
    const int nw4 = Y_ * D_ / 4;
    cvt_f16<<<(nx4 + 255) / 256, 256>>>(x, (__half*)Xh, nx4);
    cvt_f16<<<(nw4 + 255) / 256, 256>>>(U, (__half*)Uh, nw4);
    cvt_f16<<<(nw4 + 255) / 256, 256>>>(F, (__half*)Fh, nw4);

    int nsm = 148;
    cudaDeviceGetAttribute(&nsm, cudaDevAttrMultiProcessorCount, 0);
    cudaFuncSetAttribute(gemm_kernel, cudaFuncAttributeMaxDynamicSharedMemorySize, SMEM_TOT);
    gemm_kernel<<<nsm, 512, SMEM_TOT>>>();

    reduce_kernel<<<B_ * Y_ / 8, 256>>>(bias);
    loss_kernel<<<1, 256>>>(tg);
    writeout_kernel<<<(B_ * Y_ + 255) / 256, 256>>>((float*)d_out, out_size);
}